// round 5
// baseline (speedup 1.0000x reference)
#include <cuda_runtime.h>
#include <cuda_bf16.h>
#include <cstdint>

#define NB 8
#define NT 4096
#define NDIN 1024
#define NDH 1024
#define MTOT (NB * NT)   // 32768

// Scratch: interleaved (c, v) pairs per [b, t, h]. 256 MB — static device array.
__device__ float g_cv[(size_t)MTOT * NDH * 2];

// bf16 split copies (probe path): x = hi + lo, W likewise.
__device__ __nv_bfloat16 g_xhi[(size_t)MTOT * NDIN];
__device__ __nv_bfloat16 g_xlo[(size_t)MTOT * NDIN];
__device__ __nv_bfloat16 g_wzhi[(size_t)NDH * NDIN];
__device__ __nv_bfloat16 g_wzlo[(size_t)NDH * NDIN];
__device__ __nv_bfloat16 g_whhi[(size_t)NDH * NDIN];
__device__ __nv_bfloat16 g_whlo[(size_t)NDH * NDIN];
// Probe sink (prevents DCE; deterministic).
__device__ float g_probe[4096 * 256];

// ---------------------------------------------------------------------------
// Common helpers
// ---------------------------------------------------------------------------
__device__ __forceinline__ uint32_t f2tf(float f) {
    uint32_t r;
    asm("cvt.rna.tf32.f32 %0, %1;" : "=r"(r) : "f"(f));
    return r;
}

__device__ __forceinline__ void mma_tf32(float* d, const uint32_t* a, const uint32_t* b) {
    asm volatile(
        "mma.sync.aligned.m16n8k8.row.col.f32.tf32.tf32.f32 "
        "{%0,%1,%2,%3}, {%4,%5,%6,%7}, {%8,%9}, {%0,%1,%2,%3};"
        : "+f"(d[0]), "+f"(d[1]), "+f"(d[2]), "+f"(d[3])
        : "r"(a[0]), "r"(a[1]), "r"(a[2]), "r"(a[3]), "r"(b[0]), "r"(b[1]));
}

__device__ __forceinline__ void mma_bf16(float* d, const uint32_t* a, const uint32_t* b) {
    asm volatile(
        "mma.sync.aligned.m16n8k16.row.col.f32.bf16.bf16.f32 "
        "{%0,%1,%2,%3}, {%4,%5,%6,%7}, {%8,%9}, {%0,%1,%2,%3};"
        : "+f"(d[0]), "+f"(d[1]), "+f"(d[2]), "+f"(d[3])
        : "r"(a[0]), "r"(a[1]), "r"(a[2]), "r"(a[3]), "r"(b[0]), "r"(b[1]));
}

__device__ __forceinline__ void cpa16(uint32_t saddr, const void* g) {
    asm volatile("cp.async.cg.shared.global [%0], [%1], 16;" :: "r"(saddr), "l"(g));
}
__device__ __forceinline__ void cp_commit() { asm volatile("cp.async.commit_group;"); }
template <int N> __device__ __forceinline__ void cp_wait() {
    asm volatile("cp.async.wait_group %0;" :: "n"(N));
}

// c = sigmoid(-zp); v = sigmoid(zp) * g(hp)
__device__ __forceinline__ void transform(float zp, float hp, float& c, float& v) {
    const float e = __expf(-fabsf(zp));
    const float inv = __fdividef(1.0f, 1.0f + e);
    const float sp = (zp >= 0.0f) ? inv : e * inv;
    c = (zp >= 0.0f) ? e * inv : inv;
    float gh;
    if (hp >= 0.0f) {
        gh = hp + 0.5f;
    } else {
        const float e2 = __expf(hp);
        gh = __fdividef(e2, 1.0f + e2);
    }
    v = sp * gh;
}

// ---------------------------------------------------------------------------
// Prepass: split x, Wz, Wh into bf16 (hi, lo) pairs. Grid-stride, float4.
// ---------------------------------------------------------------------------
__global__ void __launch_bounds__(256)
prepass_kernel(const float* __restrict__ x,
               const float* __restrict__ Wz, const float* __restrict__ Wh)
{
    const size_t nx = (size_t)MTOT * NDIN / 4;
    const size_t nw = (size_t)NDH * NDIN / 4;
    const size_t total = nx + 2 * nw;
    for (size_t i = blockIdx.x * 256 + threadIdx.x; i < total; i += (size_t)gridDim.x * 256) {
        const float4* src;
        __nv_bfloat16 *dhi, *dlo;
        size_t k;
        if (i < nx)            { src = (const float4*)x;  dhi = g_xhi;  dlo = g_xlo;  k = i; }
        else if (i < nx + nw)  { src = (const float4*)Wz; dhi = g_wzhi; dlo = g_wzlo; k = i - nx; }
        else                   { src = (const float4*)Wh; dhi = g_whhi; dlo = g_whlo; k = i - nx - nw; }
        const float4 v = src[k];
        __nv_bfloat16 h0 = __float2bfloat16(v.x), h1 = __float2bfloat16(v.y);
        __nv_bfloat16 h2 = __float2bfloat16(v.z), h3 = __float2bfloat16(v.w);
        __nv_bfloat16 l0 = __float2bfloat16(v.x - __bfloat162float(h0));
        __nv_bfloat16 l1 = __float2bfloat16(v.y - __bfloat162float(h1));
        __nv_bfloat16 l2 = __float2bfloat16(v.z - __bfloat162float(h2));
        __nv_bfloat16 l3 = __float2bfloat16(v.w - __bfloat162float(h3));
        ((__nv_bfloat162*)dhi)[k * 2]     = __nv_bfloat162(h0, h1);
        ((__nv_bfloat162*)dhi)[k * 2 + 1] = __nv_bfloat162(h2, h3);
        ((__nv_bfloat162*)dlo)[k * 2]     = __nv_bfloat162(l0, l1);
        ((__nv_bfloat162*)dlo)[k * 2 + 1] = __nv_bfloat162(l2, l3);
    }
}

// ---------------------------------------------------------------------------
// PROBE: bf16 3-split GEMM (hi*hi + hi*lo + lo*hi), same 128x64 tiling as the
// tf32 kernel, BK=32. Writes only a dummy sink. Measures legacy bf16 mma rate.
// ---------------------------------------------------------------------------
#define PBM 128
#define PBN 64
#define PBK 32
#define PNKIT (NDIN / PBK)
#define SB 40                      // smem row stride in bf16 units (80 bytes)
#define PA_HI 0
#define PA_LO (128 * SB * 2)       // 10240
#define PBZ_HI (2 * 128 * SB * 2)  // 20480
#define PBZ_LO (PBZ_HI + 64 * SB * 2)
#define PBH_HI (PBZ_HI + 2 * 64 * SB * 2)
#define PBH_LO (PBZ_HI + 3 * 64 * SB * 2)
#define PSTAGE (PBZ_HI + 4 * 64 * SB * 2)   // 40960 bytes
#define PROBE_SMEM (2 * PSTAGE)             // 81920 bytes

__global__ void __launch_bounds__(256, 1)
gemm_bf16_probe(const void* dummy)
{
    extern __shared__ __align__(128) char ps[];
    const int tid  = threadIdx.x;
    const int lane = tid & 31;
    const int warp = tid >> 5;
    const int g    = lane >> 2;
    const int tg   = lane & 3;
    const int wm0  = (warp & 3) * 32;
    const int wn0  = (warp >> 2) * 32;
    const int mBase = blockIdx.x * PBM;
    const int nBase = blockIdx.y * PBN;

    uint32_t sbase;
    asm("{ .reg .u64 t; cvta.to.shared.u64 t, %1; cvt.u32.u64 %0, t; }" : "=r"(sbase) : "l"(ps));

    float accZ[2][4][4], accH[2][4][4];
#pragma unroll
    for (int i = 0; i < 2; i++)
#pragma unroll
        for (int j = 0; j < 4; j++)
#pragma unroll
            for (int e = 0; e < 4; e++) { accZ[i][j][e] = 0.0f; accH[i][j][e] = 0.0f; }

    auto load_stage = [&](int kt, int s) {
        const int k0 = kt * PBK;                 // bf16 elem offset
        const uint32_t so = sbase + (uint32_t)s * PSTAGE;
        // A arrays: 128 rows x 4 chunks of 16B; 2 chunks/thread/array
#pragma unroll
        for (int i = 0; i < 2; i++) {
            const int idx = tid + i * 256;
            const int r = idx >> 2;
            const int cc = idx & 3;
            const size_t gofs = (size_t)(mBase + r) * NDIN + k0 + cc * 8;
            const uint32_t sofs = (uint32_t)(r * SB * 2 + cc * 16);
            cpa16(so + PA_HI + sofs, g_xhi + gofs);
            cpa16(so + PA_LO + sofs, g_xlo + gofs);
        }
        // B arrays: 64 rows x 4 chunks; 1 chunk/thread/array
        {
            const int r = tid >> 2;
            const int cc = tid & 3;
            const size_t gofs = (size_t)(nBase + r) * NDIN + k0 + cc * 8;
            const uint32_t sofs = (uint32_t)(r * SB * 2 + cc * 16);
            cpa16(so + PBZ_HI + sofs, g_wzhi + gofs);
            cpa16(so + PBZ_LO + sofs, g_wzlo + gofs);
            cpa16(so + PBH_HI + sofs, g_whhi + gofs);
            cpa16(so + PBH_LO + sofs, g_whlo + gofs);
        }
    };

    load_stage(0, 0);
    cp_commit();

    for (int kt = 0; kt < PNKIT; kt++) {
        const int cur = kt & 1;
        if (kt + 1 < PNKIT) {
            load_stage(kt + 1, cur ^ 1);
            cp_commit();
            cp_wait<1>();
        } else {
            cp_wait<0>();
        }
        __syncthreads();

        const uint32_t sc = sbase + (uint32_t)cur * PSTAGE;
#pragma unroll
        for (int half = 0; half < 2; half++) {
            const uint32_t ho = half * 32;   // byte offset of this k16 half
            uint32_t ahi[2][4], alo[2][4];
#pragma unroll
            for (int i = 0; i < 2; i++) {
                const uint32_t r0 = (uint32_t)((wm0 + i * 16 + g) * SB * 2) + ho + tg * 4;
                const uint32_t r1 = r0 + 8 * SB * 2;
                asm volatile("ld.shared.b32 %0, [%1];" : "=r"(ahi[i][0]) : "r"(sc + PA_HI + r0));
                asm volatile("ld.shared.b32 %0, [%1];" : "=r"(ahi[i][1]) : "r"(sc + PA_HI + r1));
                asm volatile("ld.shared.b32 %0, [%1];" : "=r"(ahi[i][2]) : "r"(sc + PA_HI + r0 + 16));
                asm volatile("ld.shared.b32 %0, [%1];" : "=r"(ahi[i][3]) : "r"(sc + PA_HI + r1 + 16));
                asm volatile("ld.shared.b32 %0, [%1];" : "=r"(alo[i][0]) : "r"(sc + PA_LO + r0));
                asm volatile("ld.shared.b32 %0, [%1];" : "=r"(alo[i][1]) : "r"(sc + PA_LO + r1));
                asm volatile("ld.shared.b32 %0, [%1];" : "=r"(alo[i][2]) : "r"(sc + PA_LO + r0 + 16));
                asm volatile("ld.shared.b32 %0, [%1];" : "=r"(alo[i][3]) : "r"(sc + PA_LO + r1 + 16));
            }
#pragma unroll
            for (int j = 0; j < 4; j++) {
                const uint32_t rn = (uint32_t)((wn0 + j * 8 + g) * SB * 2) + ho + tg * 4;
                uint32_t bzh[2], bzl[2], bhh[2], bhl[2];
                asm volatile("ld.shared.b32 %0, [%1];" : "=r"(bzh[0]) : "r"(sc + PBZ_HI + rn));
                asm volatile("ld.shared.b32 %0, [%1];" : "=r"(bzh[1]) : "r"(sc + PBZ_HI + rn + 16));
                asm volatile("ld.shared.b32 %0, [%1];" : "=r"(bzl[0]) : "r"(sc + PBZ_LO + rn));
                asm volatile("ld.shared.b32 %0, [%1];" : "=r"(bzl[1]) : "r"(sc + PBZ_LO + rn + 16));
                asm volatile("ld.shared.b32 %0, [%1];" : "=r"(bhh[0]) : "r"(sc + PBH_HI + rn));
                asm volatile("ld.shared.b32 %0, [%1];" : "=r"(bhh[1]) : "r"(sc + PBH_HI + rn + 16));
                asm volatile("ld.shared.b32 %0, [%1];" : "=r"(bhl[0]) : "r"(sc + PBH_LO + rn));
                asm volatile("ld.shared.b32 %0, [%1];" : "=r"(bhl[1]) : "r"(sc + PBH_LO + rn + 16));
#pragma unroll
                for (int i = 0; i < 2; i++) {
                    mma_bf16(accZ[i][j], ahi[i], bzh);   // hi*hi
                    mma_bf16(accZ[i][j], ahi[i], bzl);   // hi*lo
                    mma_bf16(accZ[i][j], alo[i], bzh);   // lo*hi
                    mma_bf16(accH[i][j], ahi[i], bhh);
                    mma_bf16(accH[i][j], ahi[i], bhl);
                    mma_bf16(accH[i][j], alo[i], bhh);
                }
            }
        }
        __syncthreads();
    }

    // Sink (deterministic, prevents DCE)
    float s = 0.0f;
#pragma unroll
    for (int i = 0; i < 2; i++)
#pragma unroll
        for (int j = 0; j < 4; j++)
#pragma unroll
            for (int e = 0; e < 4; e++) s += accZ[i][j][e] + accH[i][j][e];
    g_probe[(blockIdx.y * gridDim.x + blockIdx.x) * 256 + tid] = s;
    (void)dummy;
}

// ---------------------------------------------------------------------------
// tf32 GEMM + transform (round-3 passing version, verbatim).
// ---------------------------------------------------------------------------
#define BM 128
#define BN 64
#define BK 16
#define NKIT (NDIN / BK)
#define SROW 20

__global__ void __launch_bounds__(256, 2)
gemm_transform_kernel(const float* __restrict__ x,
                      const float* __restrict__ Wz, const float* __restrict__ bz,
                      const float* __restrict__ Wh, const float* __restrict__ bh)
{
    __shared__ float sA[2][BM * SROW];
    __shared__ float sBz[2][BN * SROW];
    __shared__ float sBh[2][BN * SROW];

    const int tid  = threadIdx.x;
    const int lane = tid & 31;
    const int warp = tid >> 5;
    const int g    = lane >> 2;
    const int t    = lane & 3;
    const int wm0  = (warp & 3) * 32;
    const int wn0  = (warp >> 2) * 32;
    const int mBase = blockIdx.x * BM;
    const int nBase = blockIdx.y * BN;

    float accZ[2][4][4];
    float accH[2][4][4];
#pragma unroll
    for (int i = 0; i < 2; i++)
#pragma unroll
        for (int j = 0; j < 4; j++)
#pragma unroll
            for (int e = 0; e < 4; e++) { accZ[i][j][e] = 0.0f; accH[i][j][e] = 0.0f; }

    const uint32_t sA_base  = (uint32_t)__cvta_generic_to_shared(&sA[0][0]);
    const uint32_t sBz_base = (uint32_t)__cvta_generic_to_shared(&sBz[0][0]);
    const uint32_t sBh_base = (uint32_t)__cvta_generic_to_shared(&sBh[0][0]);

    auto load_stage = [&](int kt, int s) {
        const int k0 = kt * BK;
#pragma unroll
        for (int i = 0; i < 2; i++) {
            const int idx = tid + i * 256;
            const int r = idx >> 2;
            const int c = (idx & 3) * 4;
            cpa16(sA_base + (uint32_t)(s * BM * SROW + r * SROW + c) * 4u,
                  x + (size_t)(mBase + r) * NDIN + k0 + c);
        }
        {
            const int r = tid >> 2;
            const int c = (tid & 3) * 4;
            cpa16(sBz_base + (uint32_t)(s * BN * SROW + r * SROW + c) * 4u,
                  Wz + (size_t)(nBase + r) * NDIN + k0 + c);
            cpa16(sBh_base + (uint32_t)(s * BN * SROW + r * SROW + c) * 4u,
                  Wh + (size_t)(nBase + r) * NDIN + k0 + c);
        }
    };

    load_stage(0, 0);
    cp_commit();

    for (int kt = 0; kt < NKIT; kt++) {
        const int cur = kt & 1;
        if (kt + 1 < NKIT) {
            load_stage(kt + 1, cur ^ 1);
            cp_commit();
            cp_wait<1>();
        } else {
            cp_wait<0>();
        }
        __syncthreads();

        const float* As  = sA[cur];
        const float* Bzs = sBz[cur];
        const float* Bhs = sBh[cur];
#pragma unroll
        for (int kk = 0; kk < BK; kk += 8) {
            uint32_t af[2][4];
#pragma unroll
            for (int i = 0; i < 2; i++) {
                const int m = wm0 + i * 16 + g;
                af[i][0] = f2tf(As[m * SROW + kk + t]);
                af[i][1] = f2tf(As[(m + 8) * SROW + kk + t]);
                af[i][2] = f2tf(As[m * SROW + kk + t + 4]);
                af[i][3] = f2tf(As[(m + 8) * SROW + kk + t + 4]);
            }
#pragma unroll
            for (int j = 0; j < 4; j++) {
                const int n = wn0 + j * 8 + g;
                uint32_t bfz[2], bfh[2];
                bfz[0] = f2tf(Bzs[n * SROW + kk + t]);
                bfz[1] = f2tf(Bzs[n * SROW + kk + t + 4]);
                bfh[0] = f2tf(Bhs[n * SROW + kk + t]);
                bfh[1] = f2tf(Bhs[n * SROW + kk + t + 4]);
#pragma unroll
                for (int i = 0; i < 2; i++) {
                    mma_tf32(accZ[i][j], af[i], bfz);
                    mma_tf32(accH[i][j], af[i], bfh);
                }
            }
        }
        __syncthreads();
    }

#pragma unroll
    for (int j = 0; j < 4; j++) {
        const int col = nBase + wn0 + j * 8 + 2 * t;
        const float bz0 = bz[col], bz1 = bz[col + 1];
        const float bh0 = bh[col], bh1 = bh[col + 1];
#pragma unroll
        for (int i = 0; i < 2; i++) {
            const int row = mBase + wm0 + i * 16 + g;
            float c0, v0, c1, v1, c2, v2, c3, v3;
            transform(accZ[i][j][0] + bz0, accH[i][j][0] + bh0, c0, v0);
            transform(accZ[i][j][1] + bz1, accH[i][j][1] + bh1, c1, v1);
            transform(accZ[i][j][2] + bz0, accH[i][j][2] + bh0, c2, v2);
            transform(accZ[i][j][3] + bz1, accH[i][j][3] + bh1, c3, v3);
            const size_t o0 = (size_t)row * NDH + col;
            const size_t o1 = (size_t)(row + 8) * NDH + col;
            *(float4*)(g_cv + 2 * o0) = make_float4(c0, v0, c1, v1);
            *(float4*)(g_cv + 2 * o1) = make_float4(c2, v2, c3, v3);
        }
    }
}

// ---------------------------------------------------------------------------
// Scan kernel (unchanged): h_t = c_t * h_{t-1} + v_t.
// ---------------------------------------------------------------------------
__global__ void __launch_bounds__(1024)
scan_kernel(const float* __restrict__ h_prev, float* __restrict__ out)
{
    __shared__ float sc[128][33];
    __shared__ float sv[128][33];

    const int tid   = threadIdx.x;
    const int lane  = tid & 31;
    const int w     = tid >> 5;
    const int b     = blockIdx.x >> 5;
    const int hBase = (blockIdx.x & 31) << 5;

    const float hp0 = h_prev[b * NDH + hBase + w];
    float h;
    if (hp0 >= 0.0f) {
        h = hp0 + 0.5f;
    } else {
        const float e = __expf(hp0);
        h = __fdividef(e, 1.0f + e);
    }

    const int lr   = tid >> 3;
    const int hOff = (tid & 7) * 4;

    for (int t0 = 0; t0 < NT; t0 += 128) {
        const size_t rowIdx = (size_t)(b * NT + t0 + lr);
        const float* src = g_cv + rowIdx * (NDH * 2) + (size_t)(hBase + hOff) * 2;
        const float4 q0 = *(const float4*)(src);
        const float4 q1 = *(const float4*)(src + 4);
        sc[lr][hOff]     = q0.x; sv[lr][hOff]     = q0.y;
        sc[lr][hOff + 1] = q0.z; sv[lr][hOff + 1] = q0.w;
        sc[lr][hOff + 2] = q1.x; sv[lr][hOff + 2] = q1.y;
        sc[lr][hOff + 3] = q1.z; sv[lr][hOff + 3] = q1.w;
        __syncthreads();

#pragma unroll
        for (int s = 0; s < 4; s++) {
            const int tt = s * 32 + lane;
            float a  = sc[tt][w];
            float bb = sv[tt][w];
#pragma unroll
            for (int d = 1; d < 32; d <<= 1) {
                const float ap = __shfl_up_sync(0xffffffffu, a, d);
                const float bp = __shfl_up_sync(0xffffffffu, bb, d);
                if (lane >= d) {
                    bb = fmaf(a, bp, bb);
                    a *= ap;
                }
            }
            const float hn = fmaf(a, h, bb);
            sc[tt][w] = hn;
            h = __shfl_sync(0xffffffffu, hn, 31);
        }
        __syncthreads();

        float4 o;
        o.x = sc[lr][hOff]; o.y = sc[lr][hOff + 1];
        o.z = sc[lr][hOff + 2]; o.w = sc[lr][hOff + 3];
        *(float4*)(out + rowIdx * NDH + hBase + hOff) = o;
        __syncthreads();
    }
}

// ---------------------------------------------------------------------------
extern "C" void kernel_launch(void* const* d_in, const int* in_sizes, int n_in,
                              void* d_out, int out_size)
{
    (void)in_sizes; (void)n_in; (void)out_size;
    const float* x      = (const float*)d_in[0];
    const float* h_prev = (const float*)d_in[1];
    const float* Wz     = (const float*)d_in[2];
    const float* bz     = (const float*)d_in[3];
    const float* Wh     = (const float*)d_in[4];
    const float* bh     = (const float*)d_in[5];
    float* out = (float*)d_out;

    cudaFuncSetAttribute(gemm_bf16_probe,
                         cudaFuncAttributeMaxDynamicSharedMemorySize, PROBE_SMEM);

    // 4 launches/call -> ncu (-s 5) captures launch #5 = 2nd call's pos 1 =
    // gemm_bf16_probe, finally giving us GEMM-side tensor/issue metrics.
    prepass_kernel<<<2048, 256>>>(x, Wz, Wh);
    gemm_bf16_probe<<<dim3(MTOT / PBM, NDH / PBN), 256, PROBE_SMEM>>>(nullptr);
    gemm_transform_kernel<<<dim3(MTOT / BM, NDH / BN), 256>>>(x, Wz, bz, Wh, bh);
    scan_kernel<<<256, 1024>>>(h_prev, out);
}

// round 6
// speedup vs baseline: 1.9452x; 1.9452x over previous
#include <cuda_runtime.h>
#include <cuda_bf16.h>
#include <cstdint>

#define NB 8
#define NT 4096
#define NDIN 1024
#define NDH 1024
#define MTOT (NB * NT)   // 32768

// Scratch: interleaved (c, v) pairs per [b, t, h]. 256 MB — static device array.
__device__ float g_cv[(size_t)MTOT * NDH * 2];

// ---------------------------------------------------------------------------
// Helpers
// ---------------------------------------------------------------------------
__device__ __forceinline__ uint32_t f2h2(float hi_k1, float lo_k0) {
    // Packs {lo 16 bits = lo_k0, hi 16 bits = hi_k1}: cvt d, a, b -> d.hi=a, d.lo=b
    uint32_t r;
    asm("cvt.rn.f16x2.f32 %0, %1, %2;" : "=r"(r) : "f"(hi_k1), "f"(lo_k0));
    return r;
}

__device__ __forceinline__ void mma_f16(float* d, const uint32_t* a, const uint32_t* b) {
    asm volatile(
        "mma.sync.aligned.m16n8k16.row.col.f32.f16.f16.f32 "
        "{%0,%1,%2,%3}, {%4,%5,%6,%7}, {%8,%9}, {%0,%1,%2,%3};"
        : "+f"(d[0]), "+f"(d[1]), "+f"(d[2]), "+f"(d[3])
        : "r"(a[0]), "r"(a[1]), "r"(a[2]), "r"(a[3]), "r"(b[0]), "r"(b[1]));
}

__device__ __forceinline__ void cpa16(uint32_t saddr, const void* g) {
    asm volatile("cp.async.cg.shared.global [%0], [%1], 16;" :: "r"(saddr), "l"(g));
}
__device__ __forceinline__ void cp_commit() { asm volatile("cp.async.commit_group;"); }
template <int N> __device__ __forceinline__ void cp_wait() {
    asm volatile("cp.async.wait_group %0;" :: "n"(N));
}

// c = sigmoid(-zp); v = sigmoid(zp) * g(hp)
__device__ __forceinline__ void transform(float zp, float hp, float& c, float& v) {
    const float e = __expf(-fabsf(zp));
    const float inv = __fdividef(1.0f, 1.0f + e);
    const float sp = (zp >= 0.0f) ? inv : e * inv;
    c = (zp >= 0.0f) ? e * inv : inv;
    float gh;
    if (hp >= 0.0f) {
        gh = hp + 0.5f;
    } else {
        const float e2 = __expf(hp);
        gh = __fdividef(e2, 1.0f + e2);
    }
    v = sp * gh;
}

// ---------------------------------------------------------------------------
// fp16 GEMM + transform. Same blocking/pipelining as the tf32 version:
// CTA tile 128x64, BK=16 (one k16 mma fragment per tile pass), double-buffered
// cp.async staging of fp32 data; f32->f16x2 packing happens at smem->reg.
// fp16 e5m10 has the same mantissa width as tf32 -> same accuracy, half the
// mma instruction count (m16n8k16 vs m16n8k8 at equal per-instr rate).
// ---------------------------------------------------------------------------
#define BM 128
#define BN 64
#define BK 16
#define NKIT (NDIN / BK)
#define SROW 20   // padded smem row stride (floats)

__global__ void __launch_bounds__(256, 2)
gemm_transform_kernel(const float* __restrict__ x,
                      const float* __restrict__ Wz, const float* __restrict__ bz,
                      const float* __restrict__ Wh, const float* __restrict__ bh)
{
    __shared__ float sA[2][BM * SROW];
    __shared__ float sBz[2][BN * SROW];
    __shared__ float sBh[2][BN * SROW];

    const int tid  = threadIdx.x;
    const int lane = tid & 31;
    const int warp = tid >> 5;
    const int g    = lane >> 2;  // group id (0..7)
    const int t    = lane & 3;   // thread-in-group (0..3)
    const int wm0  = (warp & 3) * 32;
    const int wn0  = (warp >> 2) * 32;
    const int mBase = blockIdx.x * BM;
    const int nBase = blockIdx.y * BN;

    float accZ[2][4][4];
    float accH[2][4][4];
#pragma unroll
    for (int i = 0; i < 2; i++)
#pragma unroll
        for (int j = 0; j < 4; j++)
#pragma unroll
            for (int e = 0; e < 4; e++) { accZ[i][j][e] = 0.0f; accH[i][j][e] = 0.0f; }

    const uint32_t sA_base  = (uint32_t)__cvta_generic_to_shared(&sA[0][0]);
    const uint32_t sBz_base = (uint32_t)__cvta_generic_to_shared(&sBz[0][0]);
    const uint32_t sBh_base = (uint32_t)__cvta_generic_to_shared(&sBh[0][0]);

    auto load_stage = [&](int kt, int s) {
        const int k0 = kt * BK;
#pragma unroll
        for (int i = 0; i < 2; i++) {
            const int idx = tid + i * 256;
            const int r = idx >> 2;
            const int c = (idx & 3) * 4;
            cpa16(sA_base + (uint32_t)(s * BM * SROW + r * SROW + c) * 4u,
                  x + (size_t)(mBase + r) * NDIN + k0 + c);
        }
        {
            const int r = tid >> 2;
            const int c = (tid & 3) * 4;
            cpa16(sBz_base + (uint32_t)(s * BN * SROW + r * SROW + c) * 4u,
                  Wz + (size_t)(nBase + r) * NDIN + k0 + c);
            cpa16(sBh_base + (uint32_t)(s * BN * SROW + r * SROW + c) * 4u,
                  Wh + (size_t)(nBase + r) * NDIN + k0 + c);
        }
    };

    load_stage(0, 0);
    cp_commit();

    for (int kt = 0; kt < NKIT; kt++) {
        const int cur = kt & 1;
        if (kt + 1 < NKIT) {
            load_stage(kt + 1, cur ^ 1);
            cp_commit();
            cp_wait<1>();
        } else {
            cp_wait<0>();
        }
        __syncthreads();

        const float* As  = sA[cur];
        const float* Bzs = sBz[cur];
        const float* Bhs = sBh[cur];

        // A fragments: a0=(row, k=2t..2t+1), a1=(row+8, k), a2=(row, k+8), a3=(row+8, k+8)
        uint32_t af[2][4];
#pragma unroll
        for (int i = 0; i < 2; i++) {
            const int m = wm0 + i * 16 + g;
            const float2 p0 = *(const float2*)&As[m * SROW + 2 * t];
            const float2 p1 = *(const float2*)&As[(m + 8) * SROW + 2 * t];
            const float2 p2 = *(const float2*)&As[m * SROW + 2 * t + 8];
            const float2 p3 = *(const float2*)&As[(m + 8) * SROW + 2 * t + 8];
            af[i][0] = f2h2(p0.y, p0.x);
            af[i][1] = f2h2(p1.y, p1.x);
            af[i][2] = f2h2(p2.y, p2.x);
            af[i][3] = f2h2(p3.y, p3.x);
        }
#pragma unroll
        for (int j = 0; j < 4; j++) {
            const int n = wn0 + j * 8 + g;
            const float2 qz0 = *(const float2*)&Bzs[n * SROW + 2 * t];
            const float2 qz1 = *(const float2*)&Bzs[n * SROW + 2 * t + 8];
            const float2 qh0 = *(const float2*)&Bhs[n * SROW + 2 * t];
            const float2 qh1 = *(const float2*)&Bhs[n * SROW + 2 * t + 8];
            uint32_t bfz[2], bfh[2];
            bfz[0] = f2h2(qz0.y, qz0.x);
            bfz[1] = f2h2(qz1.y, qz1.x);
            bfh[0] = f2h2(qh0.y, qh0.x);
            bfh[1] = f2h2(qh1.y, qh1.x);
#pragma unroll
            for (int i = 0; i < 2; i++) {
                mma_f16(accZ[i][j], af[i], bfz);
                mma_f16(accH[i][j], af[i], bfh);
            }
        }
        __syncthreads();
    }

    // Epilogue: bias + transform + store interleaved (c, v) as float4 pairs.
#pragma unroll
    for (int j = 0; j < 4; j++) {
        const int col = nBase + wn0 + j * 8 + 2 * t;   // even
        const float bz0 = bz[col], bz1 = bz[col + 1];
        const float bh0 = bh[col], bh1 = bh[col + 1];
#pragma unroll
        for (int i = 0; i < 2; i++) {
            const int row = mBase + wm0 + i * 16 + g;
            float c0, v0, c1, v1, c2, v2, c3, v3;
            transform(accZ[i][j][0] + bz0, accH[i][j][0] + bh0, c0, v0);
            transform(accZ[i][j][1] + bz1, accH[i][j][1] + bh1, c1, v1);
            transform(accZ[i][j][2] + bz0, accH[i][j][2] + bh0, c2, v2);
            transform(accZ[i][j][3] + bz1, accH[i][j][3] + bh1, c3, v3);
            const size_t o0 = (size_t)row * NDH + col;
            const size_t o1 = (size_t)(row + 8) * NDH + col;
            *(float4*)(g_cv + 2 * o0) = make_float4(c0, v0, c1, v1);
            *(float4*)(g_cv + 2 * o1) = make_float4(c2, v2, c3, v3);
        }
    }
}

// ---------------------------------------------------------------------------
// Scan kernel (unchanged): h_t = c_t * h_{t-1} + v_t.
// ---------------------------------------------------------------------------
__global__ void __launch_bounds__(1024)
scan_kernel(const float* __restrict__ h_prev, float* __restrict__ out)
{
    __shared__ float sc[128][33];
    __shared__ float sv[128][33];

    const int tid   = threadIdx.x;
    const int lane  = tid & 31;
    const int w     = tid >> 5;
    const int b     = blockIdx.x >> 5;
    const int hBase = (blockIdx.x & 31) << 5;

    const float hp0 = h_prev[b * NDH + hBase + w];
    float h;
    if (hp0 >= 0.0f) {
        h = hp0 + 0.5f;
    } else {
        const float e = __expf(hp0);
        h = __fdividef(e, 1.0f + e);
    }

    const int lr   = tid >> 3;
    const int hOff = (tid & 7) * 4;

    for (int t0 = 0; t0 < NT; t0 += 128) {
        const size_t rowIdx = (size_t)(b * NT + t0 + lr);
        const float* src = g_cv + rowIdx * (NDH * 2) + (size_t)(hBase + hOff) * 2;
        const float4 q0 = *(const float4*)(src);
        const float4 q1 = *(const float4*)(src + 4);
        sc[lr][hOff]     = q0.x; sv[lr][hOff]     = q0.y;
        sc[lr][hOff + 1] = q0.z; sv[lr][hOff + 1] = q0.w;
        sc[lr][hOff + 2] = q1.x; sv[lr][hOff + 2] = q1.y;
        sc[lr][hOff + 3] = q1.z; sv[lr][hOff + 3] = q1.w;
        __syncthreads();

#pragma unroll
        for (int s = 0; s < 4; s++) {
            const int tt = s * 32 + lane;
            float a  = sc[tt][w];
            float bb = sv[tt][w];
#pragma unroll
            for (int d = 1; d < 32; d <<= 1) {
                const float ap = __shfl_up_sync(0xffffffffu, a, d);
                const float bp = __shfl_up_sync(0xffffffffu, bb, d);
                if (lane >= d) {
                    bb = fmaf(a, bp, bb);
                    a *= ap;
                }
            }
            const float hn = fmaf(a, h, bb);
            sc[tt][w] = hn;
            h = __shfl_sync(0xffffffffu, hn, 31);
        }
        __syncthreads();

        float4 o;
        o.x = sc[lr][hOff]; o.y = sc[lr][hOff + 1];
        o.z = sc[lr][hOff + 2]; o.w = sc[lr][hOff + 3];
        *(float4*)(out + rowIdx * NDH + hBase + hOff) = o;
        __syncthreads();
    }
}

// Empty guard kernel: shifts launch indexing so ncu (-s 5 -c 1) captures the
// GEMM (sequence per call: guard, gemm, scan, guard -> global idx 5 = gemm).
__global__ void guard_kernel() {}

// ---------------------------------------------------------------------------
extern "C" void kernel_launch(void* const* d_in, const int* in_sizes, int n_in,
                              void* d_out, int out_size)
{
    (void)in_sizes; (void)n_in; (void)out_size;
    const float* x      = (const float*)d_in[0];
    const float* h_prev = (const float*)d_in[1];
    const float* Wz     = (const float*)d_in[2];
    const float* bz     = (const float*)d_in[3];
    const float* Wh     = (const float*)d_in[4];
    const float* bh     = (const float*)d_in[5];
    float* out = (float*)d_out;

    guard_kernel<<<1, 32>>>();
    gemm_transform_kernel<<<dim3(MTOT / BM, NDH / BN), 256>>>(x, Wz, bz, Wh, bh);
    scan_kernel<<<256, 1024>>>(h_prev, out);
    guard_kernel<<<1, 32>>>();
}